// round 15
// baseline (speedup 1.0000x reference)
#include <cuda_runtime.h>
#include <cuda_bf16.h>
#include <cstdint>

#define N_NODES 100000
#define N_EDGES 1600000
#define NODE_DIM 64
#define HIDDEN 256
#define OUT_DIM 64
#define BN_EPS 1e-5f
#define BUCKET 64     /* slots per node; P(deg>64) ~ 1e-13 for Poisson(16) */
#define MLP_TILE 256
#define N_TILES2 391  /* ceil(100000/256) */

// ---- device scratch (no allocation allowed) ----
__device__ float g_x[N_NODES * NODE_DIM];       // combined input x = agg/deg + h
__device__ int   g_cnt[N_NODES];                // in-degree (and scatter cursor)
__device__ int   g_esrc[N_NODES * BUCKET];      // bucket CSR edge sources
__device__ float g_colsum[OUT_DIM];
__device__ float g_colsq[OUT_DIM];

// ===========================================================================
// helpers (base ISA only — harness targets compute_103, no 'a' features)
// ===========================================================================
__device__ __forceinline__ uint32_t smem_u32(const void* p) {
    uint32_t a;
    asm("{ .reg .u64 t; cvta.to.shared.u64 t, %1; cvt.u32.u64 %0, t; }" : "=r"(a) : "l"(p));
    return a;
}
__device__ __forceinline__ void ldsm4(uint32_t* r, uint32_t addr) {
    asm volatile("ldmatrix.sync.aligned.m8n8.x4.shared.b16 {%0,%1,%2,%3}, [%4];"
                 : "=r"(r[0]), "=r"(r[1]), "=r"(r[2]), "=r"(r[3]) : "r"(addr));
}
__device__ __forceinline__ void mma16816(float* d, const uint32_t* a, uint32_t b0, uint32_t b1) {
    asm volatile("mma.sync.aligned.m16n8k16.row.col.f32.bf16.bf16.f32 "
                 "{%0,%1,%2,%3}, {%4,%5,%6,%7}, {%8,%9}, {%0,%1,%2,%3};"
                 : "+f"(d[0]), "+f"(d[1]), "+f"(d[2]), "+f"(d[3])
                 : "r"(a[0]), "r"(a[1]), "r"(a[2]), "r"(a[3]), "r"(b0), "r"(b1));
}
__device__ __forceinline__ uint32_t packbf(float a, float b) {
    __nv_bfloat162 t = __floats2bfloat162_rn(a, b);
    return *reinterpret_cast<uint32_t*>(&t);
}
__device__ __forceinline__ float bf_lo(uint32_t p) { return __uint_as_float(p << 16); }
__device__ __forceinline__ float bf_hi(uint32_t p) { return __uint_as_float(p & 0xffff0000u); }

// ---------------------------------------------------------------------------
// 1: zero counters
// ---------------------------------------------------------------------------
__global__ void zero_kernel() {
    int i = blockIdx.x * 256 + threadIdx.x;
    if (i < N_NODES) g_cnt[i] = 0;
    if (i < OUT_DIM) { g_colsum[i] = 0.0f; g_colsq[i] = 0.0f; }
}

// ---------------------------------------------------------------------------
// 2: bucket scatter — atomic cursor doubles as the in-degree count.
// ---------------------------------------------------------------------------
__global__ void scatter_kernel(const int* __restrict__ src,
                               const int* __restrict__ dst) {
    int i = blockIdx.x * 256 + threadIdx.x;
    if (i >= N_EDGES) return;
    int d = dst[i];
    int pos = atomicAdd(&g_cnt[d], 1);
    if (pos < BUCKET) g_esrc[(d << 6) + pos] = src[i];
}

// ---------------------------------------------------------------------------
// 3: warp-per-node gather + mean + combine: g_x = agg/max(deg,1) + h
// ---------------------------------------------------------------------------
__global__ void agg_kernel(const float* __restrict__ h) {
    int n = (blockIdx.x * 256 + threadIdx.x) >> 5;
    if (n >= N_NODES) return;
    int lane = threadIdx.x & 31;
    int deg = __ldg(&g_cnt[n]);
    if (deg > BUCKET) deg = BUCKET;
    int beg = n << 6;
    float ax = 0.0f, ay = 0.0f;

    int nfull = deg & ~31;
    int j = 0;
    for (; j < nfull; j += 32) {
        int s_l = __ldg(&g_esrc[beg + j + lane]);
#pragma unroll
        for (int jj = 0; jj < 32; jj++) {
            int s = __shfl_sync(0xffffffffu, s_l, jj);
            float2 v = *(const float2*)(h + ((size_t)s << 6) + (lane << 1));
            ax += v.x;
            ay += v.y;
        }
    }
    int rem = deg & 31;
    if (rem) {
        int s_l = (lane < rem) ? __ldg(&g_esrc[beg + j + lane]) : 0;
        for (int jj = 0; jj < rem; jj++) {
            int s = __shfl_sync(0xffffffffu, s_l, jj);
            float2 v = *(const float2*)(h + ((size_t)s << 6) + (lane << 1));
            ax += v.x;
            ay += v.y;
        }
    }
    float inv = 1.0f / fmaxf((float)deg, 1.0f);
    float2 hv = *(const float2*)(h + ((size_t)n << 6) + (lane << 1));
    float2 xv = make_float2(fmaf(ax, inv, hv.x), fmaf(ay, inv, hv.y));
    *(float2*)(g_x + ((size_t)n << 6) + (lane << 1)) = xv;
}

// ---------------------------------------------------------------------------
// 4: warp-MMA bf16 split MLP — 256 threads (8 warps), m32 per warp.
//    Each B fragment load now feeds TWO m16 A sets: halves smem B traffic.
// ---------------------------------------------------------------------------
#define SM_XH  0          /* x  hi  [256][72] bf16 = 36864 B */
#define SM_XL  36864      /* x  lo  */
#define SM_W1H 73728      /* W1T hi [256][72] bf16 */
#define SM_W1L 110592
#define SM_W2H 147456     /* W2T hi [64][264] bf16 */
#define SM_W2L 181248
#define SM_B1  215040     /* float[256] */
#define SM_B2  216064     /* float[64]  */
#define SMEM_MLP 216320   /* 211.25 KB */

__global__ void __launch_bounds__(256, 1)
mlp_mma_kernel(const float* __restrict__ W1, const float* __restrict__ b1,
               const float* __restrict__ W2, const float* __restrict__ b2,
               float* __restrict__ out) {
    extern __shared__ __align__(16) char sm[];
    const uint32_t sbase = smem_u32(sm);
    int tid = threadIdx.x, lane = tid & 31, wid = tid >> 5;

    __nv_bfloat16* w1h = (__nv_bfloat16*)(sm + SM_W1H);
    __nv_bfloat16* w1l = (__nv_bfloat16*)(sm + SM_W1L);
    for (int idx = tid; idx < 64 * 256; idx += 256) {
        int k = idx >> 8, n = idx & 255;
        float w = W1[idx];
        __nv_bfloat16 hv = __float2bfloat16(w);
        w1h[n * 72 + k] = hv;
        w1l[n * 72 + k] = __float2bfloat16(w - __bfloat162float(hv));
    }
    __nv_bfloat16* w2h = (__nv_bfloat16*)(sm + SM_W2H);
    __nv_bfloat16* w2l = (__nv_bfloat16*)(sm + SM_W2L);
    for (int idx = tid; idx < 256 * 64; idx += 256) {
        int k = idx >> 6, n = idx & 63;
        float w = W2[idx];
        __nv_bfloat16 hv = __float2bfloat16(w);
        w2h[n * 264 + k] = hv;
        w2l[n * 264 + k] = __float2bfloat16(w - __bfloat162float(hv));
    }
    ((float*)(sm + SM_B1))[tid] = b1[tid];
    if (tid < 64) ((float*)(sm + SM_B2))[tid] = b2[tid];
    __syncthreads();

    __nv_bfloat16* xh = (__nv_bfloat16*)(sm + SM_XH);
    __nv_bfloat16* xl = (__nv_bfloat16*)(sm + SM_XL);
    const float* b1s = (const float*)(sm + SM_B1);
    const float* b2s = (const float*)(sm + SM_B2);

    for (int tile = blockIdx.x; tile < N_TILES2; tile += gridDim.x) {
        // ---- stage 256-row x tile: one thread per row ----
        {
            int node = tile * MLP_TILE + tid;
            const float4* p = (const float4*)(g_x + (size_t)node * 64);
            __nv_bfloat16* dh = xh + tid * 72;
            __nv_bfloat16* dl = xl + tid * 72;
#pragma unroll
            for (int q = 0; q < 16; q++) {
                float4 v = (node < N_NODES) ? p[q] : make_float4(0.f, 0.f, 0.f, 0.f);
                float vv[4] = {v.x, v.y, v.z, v.w};
#pragma unroll
                for (int j = 0; j < 4; j++) {
                    __nv_bfloat16 hv = __float2bfloat16(vv[j]);
                    dh[4 * q + j] = hv;
                    dl[4 * q + j] = __float2bfloat16(vv[j] - __bfloat162float(hv));
                }
            }
        }
        __syncthreads();

        // ---- A1 fragments for both row sets (rows wid*32 + rs*16 ..) ----
        uint32_t a1h[2][4][4], a1l[2][4][4];
#pragma unroll
        for (int rs = 0; rs < 2; rs++)
#pragma unroll
            for (int kt = 0; kt < 4; kt++) {
                uint32_t addr = sbase + SM_XH +
                    (uint32_t)(wid * 32 + rs * 16 + (lane & 15)) * 144u +
                    (uint32_t)(kt * 16 + ((lane >> 4) << 3)) * 2u;
                ldsm4(a1h[rs][kt], addr);
                ldsm4(a1l[rs][kt], addr + (SM_XL - SM_XH));
            }

        float d2[2][8][4];
#pragma unroll
        for (int rs = 0; rs < 2; rs++)
#pragma unroll
            for (int i = 0; i < 8; i++)
#pragma unroll
                for (int j = 0; j < 4; j++) d2[rs][i][j] = 0.0f;

#pragma unroll 1
        for (int nc = 0; nc < 16; nc++) {
            float c[2][8];
#pragma unroll
            for (int rs = 0; rs < 2; rs++)
#pragma unroll
                for (int i = 0; i < 8; i++) c[rs][i] = 0.0f;

            uint32_t bb = sbase + SM_W1H +
                (uint32_t)(nc * 16 + (lane & 7) + ((lane >> 4) & 1) * 8) * 144u + ((lane >> 3) & 1) * 16u;
#pragma unroll
            for (int kt = 0; kt < 4; kt++) {
                uint32_t bh[4], bl[4];
                ldsm4(bh, bb + kt * 32u);
                ldsm4(bl, bb + kt * 32u + (SM_W1L - SM_W1H));
#pragma unroll
                for (int rs = 0; rs < 2; rs++) {
                    mma16816(c[rs] + 0, a1h[rs][kt], bh[0], bh[1]);
                    mma16816(c[rs] + 4, a1h[rs][kt], bh[2], bh[3]);
                    mma16816(c[rs] + 0, a1h[rs][kt], bl[0], bl[1]);
                    mma16816(c[rs] + 4, a1h[rs][kt], bl[2], bl[3]);
                    mma16816(c[rs] + 0, a1l[rs][kt], bh[0], bh[1]);
                    mma16816(c[rs] + 4, a1l[rs][kt], bh[2], bh[3]);
                }
            }

            // ---- epilogue1: relu(H+b1) -> A2 fragments, both row sets ----
            int cb = nc * 16 + (lane & 3) * 2;
            float2 bb0 = *(const float2*)&b1s[cb];
            float2 bb1 = *(const float2*)&b1s[cb + 8];
            uint32_t a2h[2][4], a2l[2][4];
#pragma unroll
            for (int rs = 0; rs < 2; rs++) {
                float v00 = fmaxf(c[rs][0] + bb0.x, 0.f), v01 = fmaxf(c[rs][1] + bb0.y, 0.f);
                float v10 = fmaxf(c[rs][2] + bb0.x, 0.f), v11 = fmaxf(c[rs][3] + bb0.y, 0.f);
                float w00 = fmaxf(c[rs][4] + bb1.x, 0.f), w01 = fmaxf(c[rs][5] + bb1.y, 0.f);
                float w10 = fmaxf(c[rs][6] + bb1.x, 0.f), w11 = fmaxf(c[rs][7] + bb1.y, 0.f);
                a2h[rs][0] = packbf(v00, v01); a2l[rs][0] = packbf(v00 - bf_lo(a2h[rs][0]), v01 - bf_hi(a2h[rs][0]));
                a2h[rs][1] = packbf(v10, v11); a2l[rs][1] = packbf(v10 - bf_lo(a2h[rs][1]), v11 - bf_hi(a2h[rs][1]));
                a2h[rs][2] = packbf(w00, w01); a2l[rs][2] = packbf(w00 - bf_lo(a2h[rs][2]), w01 - bf_hi(a2h[rs][2]));
                a2h[rs][3] = packbf(w10, w11); a2l[rs][3] = packbf(w10 - bf_lo(a2h[rs][3]), w11 - bf_hi(a2h[rs][3]));
            }

            // ---- GEMM2: one B load feeds both row sets ----
            uint32_t b2b = sbase + SM_W2H +
                (uint32_t)((lane & 7) + ((lane >> 4) & 1) * 8) * 528u + (uint32_t)nc * 32u + ((lane >> 3) & 1) * 16u;
#pragma unroll
            for (int np = 0; np < 4; np++) {
                uint32_t bh[4], bl[4];
                ldsm4(bh, b2b + (uint32_t)np * (16u * 528u));
                ldsm4(bl, b2b + (uint32_t)np * (16u * 528u) + (SM_W2L - SM_W2H));
#pragma unroll
                for (int rs = 0; rs < 2; rs++) {
                    mma16816(d2[rs][2 * np],     a2h[rs], bh[0], bh[1]);
                    mma16816(d2[rs][2 * np + 1], a2h[rs], bh[2], bh[3]);
                    mma16816(d2[rs][2 * np],     a2h[rs], bl[0], bl[1]);
                    mma16816(d2[rs][2 * np + 1], a2h[rs], bl[2], bl[3]);
                    mma16816(d2[rs][2 * np],     a2l[rs], bh[0], bh[1]);
                    mma16816(d2[rs][2 * np + 1], a2l[rs], bh[2], bh[3]);
                }
            }
        }

        // ---- epilogue2: relu(D2+b2) -> out, both row sets ----
        int colb = (lane & 3) * 2;
#pragma unroll
        for (int rs = 0; rs < 2; rs++) {
            int row0 = tile * MLP_TILE + wid * 32 + rs * 16 + (lane >> 2);
#pragma unroll
            for (int t = 0; t < 8; t++) {
                int col = t * 8 + colb;
                if (row0 < N_NODES) {
                    float2 o;
                    o.x = fmaxf(d2[rs][t][0] + b2s[col], 0.f);
                    o.y = fmaxf(d2[rs][t][1] + b2s[col + 1], 0.f);
                    *(float2*)(out + (size_t)row0 * 64 + col) = o;
                }
                if (row0 + 8 < N_NODES) {
                    float2 o;
                    o.x = fmaxf(d2[rs][t][2] + b2s[col], 0.f);
                    o.y = fmaxf(d2[rs][t][3] + b2s[col + 1], 0.f);
                    *(float2*)(out + (size_t)(row0 + 8) * 64 + col) = o;
                }
            }
        }
        __syncthreads();
    }
}

// ---------------------------------------------------------------------------
// 5: BN column stats
// ---------------------------------------------------------------------------
__global__ void stats_kernel(const float* __restrict__ y) {
    __shared__ float ss[64], sq[64];
    if (threadIdx.x < 64) { ss[threadIdx.x] = 0.0f; sq[threadIdx.x] = 0.0f; }
    __syncthreads();
    const float4* y4 = (const float4*)y;
    const int total = N_NODES * 16;
    int i0 = blockIdx.x * 256 + threadIdx.x;
    int c4 = (i0 & 15) << 2;
    float4 s = make_float4(0.f, 0.f, 0.f, 0.f);
    float4 q = make_float4(0.f, 0.f, 0.f, 0.f);
    for (int i = i0; i < total; i += gridDim.x * 256) {
        float4 v = y4[i];
        s.x += v.x; s.y += v.y; s.z += v.z; s.w += v.w;
        q.x = fmaf(v.x, v.x, q.x);
        q.y = fmaf(v.y, v.y, q.y);
        q.z = fmaf(v.z, v.z, q.z);
        q.w = fmaf(v.w, v.w, q.w);
    }
    atomicAdd(&ss[c4 + 0], s.x); atomicAdd(&ss[c4 + 1], s.y);
    atomicAdd(&ss[c4 + 2], s.z); atomicAdd(&ss[c4 + 3], s.w);
    atomicAdd(&sq[c4 + 0], q.x); atomicAdd(&sq[c4 + 1], q.y);
    atomicAdd(&sq[c4 + 2], q.z); atomicAdd(&sq[c4 + 3], q.w);
    __syncthreads();
    if (threadIdx.x < 64) {
        atomicAdd(&g_colsum[threadIdx.x], ss[threadIdx.x]);
        atomicAdd(&g_colsq[threadIdx.x], sq[threadIdx.x]);
    }
}

// ---------------------------------------------------------------------------
// 6: BN apply in place
// ---------------------------------------------------------------------------
__global__ void bn_kernel(float* __restrict__ y,
                          const float* __restrict__ gamma,
                          const float* __restrict__ beta) {
    __shared__ float scale[64], shift[64];
    if (threadIdx.x < 64) {
        int c = threadIdx.x;
        const float invN = 1.0f / (float)N_NODES;
        float mean = g_colsum[c] * invN;
        float var = fmaxf(g_colsq[c] * invN - mean * mean, 0.0f);
        float sc = gamma[c] * rsqrtf(var + BN_EPS);
        scale[c] = sc;
        shift[c] = beta[c] - mean * sc;
    }
    __syncthreads();
    int i = blockIdx.x * blockDim.x + threadIdx.x;
    int stride = gridDim.x * blockDim.x;
    const int total4 = N_NODES * OUT_DIM / 4;
    float4* y4 = (float4*)y;
    for (; i < total4; i += stride) {
        int c4 = (i & 15) * 4;
        float4 v = y4[i];
        v.x = fmaf(v.x, scale[c4 + 0], shift[c4 + 0]);
        v.y = fmaf(v.y, scale[c4 + 1], shift[c4 + 1]);
        v.z = fmaf(v.z, scale[c4 + 2], shift[c4 + 2]);
        v.w = fmaf(v.w, scale[c4 + 3], shift[c4 + 3]);
        y4[i] = v;
    }
}

// ---------------------------------------------------------------------------
extern "C" void kernel_launch(void* const* d_in, const int* in_sizes, int n_in,
                              void* d_out, int out_size) {
    const float* h     = (const float*)d_in[0];
    const float* W1    = (const float*)d_in[1];
    const float* b1    = (const float*)d_in[2];
    const float* W2    = (const float*)d_in[3];
    const float* b2    = (const float*)d_in[4];
    const float* gamma = (const float*)d_in[5];
    const float* beta  = (const float*)d_in[6];
    const int*   src   = (const int*)d_in[7];
    const int*   dst   = (const int*)d_in[8];
    float* out = (float*)d_out;

    cudaFuncSetAttribute(mlp_mma_kernel, cudaFuncAttributeMaxDynamicSharedMemorySize, SMEM_MLP);

    zero_kernel<<<(N_NODES + 255) / 256, 256>>>();
    scatter_kernel<<<(N_EDGES + 255) / 256, 256>>>(src, dst);
    agg_kernel<<<(N_NODES * 32 + 255) / 256, 256>>>(h);
    mlp_mma_kernel<<<148, 256, SMEM_MLP>>>(W1, b1, W2, b2, out);
    stats_kernel<<<1024, 256>>>(out);
    bn_kernel<<<2048, 256>>>(out, gamma, beta);
}

// round 16
// speedup vs baseline: 1.0956x; 1.0956x over previous
#include <cuda_runtime.h>
#include <cuda_bf16.h>
#include <cstdint>

#define N_NODES 100000
#define N_EDGES 1600000
#define NODE_DIM 64
#define HIDDEN 256
#define OUT_DIM 64
#define BN_EPS 1e-5f
#define BUCKET 64     /* slots per node; P(deg>64) ~ 1e-13 for Poisson(16) */
#define MLP_TILE 256
#define N_TILES2 391  /* ceil(100000/256) */

// ---- device scratch (no allocation allowed) ----
__device__ float g_x[N_NODES * NODE_DIM];       // combined input x = agg/deg + h
__device__ int   g_cnt[N_NODES];                // in-degree (and scatter cursor)
__device__ int   g_esrc[N_NODES * BUCKET];      // bucket CSR edge sources
__device__ float g_colsum[OUT_DIM];
__device__ float g_colsq[OUT_DIM];

// ===========================================================================
// helpers (base ISA only — harness targets compute_103, no 'a' features)
// ===========================================================================
__device__ __forceinline__ uint32_t smem_u32(const void* p) {
    uint32_t a;
    asm("{ .reg .u64 t; cvta.to.shared.u64 t, %1; cvt.u32.u64 %0, t; }" : "=r"(a) : "l"(p));
    return a;
}
__device__ __forceinline__ void ldsm4(uint32_t* r, uint32_t addr) {
    asm volatile("ldmatrix.sync.aligned.m8n8.x4.shared.b16 {%0,%1,%2,%3}, [%4];"
                 : "=r"(r[0]), "=r"(r[1]), "=r"(r[2]), "=r"(r[3]) : "r"(addr));
}
__device__ __forceinline__ void mma16816(float* d, const uint32_t* a, uint32_t b0, uint32_t b1) {
    asm volatile("mma.sync.aligned.m16n8k16.row.col.f32.bf16.bf16.f32 "
                 "{%0,%1,%2,%3}, {%4,%5,%6,%7}, {%8,%9}, {%0,%1,%2,%3};"
                 : "+f"(d[0]), "+f"(d[1]), "+f"(d[2]), "+f"(d[3])
                 : "r"(a[0]), "r"(a[1]), "r"(a[2]), "r"(a[3]), "r"(b0), "r"(b1));
}
__device__ __forceinline__ uint32_t packbf(float a, float b) {
    __nv_bfloat162 t = __floats2bfloat162_rn(a, b);
    return *reinterpret_cast<uint32_t*>(&t);
}
__device__ __forceinline__ float bf_lo(uint32_t p) { return __uint_as_float(p << 16); }
__device__ __forceinline__ float bf_hi(uint32_t p) { return __uint_as_float(p & 0xffff0000u); }

// ---------------------------------------------------------------------------
// 1: zero counters
// ---------------------------------------------------------------------------
__global__ void zero_kernel() {
    int i = blockIdx.x * 256 + threadIdx.x;
    if (i < N_NODES) g_cnt[i] = 0;
    if (i < OUT_DIM) { g_colsum[i] = 0.0f; g_colsq[i] = 0.0f; }
}

// ---------------------------------------------------------------------------
// 2: bucket scatter — atomic cursor doubles as the in-degree count.
// ---------------------------------------------------------------------------
__global__ void scatter_kernel(const int* __restrict__ src,
                               const int* __restrict__ dst) {
    int i = blockIdx.x * 256 + threadIdx.x;
    if (i >= N_EDGES) return;
    int d = dst[i];
    int pos = atomicAdd(&g_cnt[d], 1);
    if (pos < BUCKET) g_esrc[(d << 6) + pos] = src[i];
}

// ---------------------------------------------------------------------------
// 3: warp-per-node gather + mean + combine: g_x = agg/max(deg,1) + h
//    Batched-8 inner loop: all 8 loads issue before any accumulate consumes
//    (the old dynamic remainder loop serialized ~16 x 250cyc per warp).
// ---------------------------------------------------------------------------
__global__ void agg_kernel(const float* __restrict__ h) {
    int n = (blockIdx.x * 256 + threadIdx.x) >> 5;
    if (n >= N_NODES) return;
    int lane = threadIdx.x & 31;
    int deg = __ldg(&g_cnt[n]);
    if (deg > BUCKET) deg = BUCKET;
    int beg = n << 6;
    float ax = 0.0f, ay = 0.0f;

    if (deg > 0) {
        // preload all (<=64) edge sources; slots past deg are garbage but
        // never dereferenced (indices clamped to edge 0's source below).
        int s_l0 = __ldg(&g_esrc[beg + lane]);
        int s_l1 = (deg > 32) ? __ldg(&g_esrc[beg + 32 + lane]) : 0;
        int s_safe = __shfl_sync(0xffffffffu, s_l0, 0);

        for (int j0 = 0; j0 < deg; j0 += 8) {
            int breg = (j0 < 32) ? s_l0 : s_l1;
#pragma unroll
            for (int k = 0; k < 8; k++) {
                int jj = j0 + k;
                int s = __shfl_sync(0xffffffffu, breg, jj & 31);
                bool valid = jj < deg;          // warp-uniform
                s = valid ? s : s_safe;         // always a safe address
                float2 v = *(const float2*)(h + ((size_t)s << 6) + (lane << 1));
                if (valid) { ax += v.x; ay += v.y; }
            }
        }
    }
    float inv = 1.0f / fmaxf((float)deg, 1.0f);
    float2 hv = *(const float2*)(h + ((size_t)n << 6) + (lane << 1));
    float2 xv = make_float2(fmaf(ax, inv, hv.x), fmaf(ay, inv, hv.y));
    *(float2*)(g_x + ((size_t)n << 6) + (lane << 1)) = xv;
}

// ---------------------------------------------------------------------------
// 4: warp-MMA bf16 split MLP — round-13 config (512 thr, 16 warps, m16/warp,
//    256-row tiles). Known 73us; m32 variant regressed (regs 201, occ 12.5%).
// ---------------------------------------------------------------------------
#define SM_XH  0          /* x  hi  [256][72] bf16 = 36864 B */
#define SM_XL  36864      /* x  lo  */
#define SM_W1H 73728      /* W1T hi [256][72] bf16 */
#define SM_W1L 110592
#define SM_W2H 147456     /* W2T hi [64][264] bf16 */
#define SM_W2L 181248
#define SM_B1  215040     /* float[256] */
#define SM_B2  216064     /* float[64]  */
#define SMEM_MLP 216320   /* 211.25 KB */

__global__ void __launch_bounds__(512, 1)
mlp_mma_kernel(const float* __restrict__ W1, const float* __restrict__ b1,
               const float* __restrict__ W2, const float* __restrict__ b2,
               float* __restrict__ out) {
    extern __shared__ __align__(16) char sm[];
    const uint32_t sbase = smem_u32(sm);
    int tid = threadIdx.x, lane = tid & 31, wid = tid >> 5;

    __nv_bfloat16* w1h = (__nv_bfloat16*)(sm + SM_W1H);
    __nv_bfloat16* w1l = (__nv_bfloat16*)(sm + SM_W1L);
    for (int idx = tid; idx < 64 * 256; idx += 512) {
        int k = idx >> 8, n = idx & 255;
        float w = W1[idx];
        __nv_bfloat16 hv = __float2bfloat16(w);
        w1h[n * 72 + k] = hv;
        w1l[n * 72 + k] = __float2bfloat16(w - __bfloat162float(hv));
    }
    __nv_bfloat16* w2h = (__nv_bfloat16*)(sm + SM_W2H);
    __nv_bfloat16* w2l = (__nv_bfloat16*)(sm + SM_W2L);
    for (int idx = tid; idx < 256 * 64; idx += 512) {
        int k = idx >> 6, n = idx & 63;
        float w = W2[idx];
        __nv_bfloat16 hv = __float2bfloat16(w);
        w2h[n * 264 + k] = hv;
        w2l[n * 264 + k] = __float2bfloat16(w - __bfloat162float(hv));
    }
    ((float*)(sm + SM_B1))[tid & 255] = b1[tid & 255];
    if (tid < 64) ((float*)(sm + SM_B2))[tid] = b2[tid];
    __syncthreads();

    __nv_bfloat16* xh = (__nv_bfloat16*)(sm + SM_XH);
    __nv_bfloat16* xl = (__nv_bfloat16*)(sm + SM_XL);
    const float* b1s = (const float*)(sm + SM_B1);
    const float* b2s = (const float*)(sm + SM_B2);

    for (int tile = blockIdx.x; tile < N_TILES2; tile += gridDim.x) {
        {
            int r = tid >> 1;
            int node = tile * MLP_TILE + r;
            int co = (tid & 1) * 32;
            const float4* p = (const float4*)(g_x + (size_t)node * 64 + co);
            __nv_bfloat16* dh = xh + r * 72 + co;
            __nv_bfloat16* dl = xl + r * 72 + co;
#pragma unroll
            for (int q = 0; q < 8; q++) {
                float4 v = (node < N_NODES) ? p[q] : make_float4(0.f, 0.f, 0.f, 0.f);
                float vv[4] = {v.x, v.y, v.z, v.w};
#pragma unroll
                for (int j = 0; j < 4; j++) {
                    __nv_bfloat16 hv = __float2bfloat16(vv[j]);
                    dh[4 * q + j] = hv;
                    dl[4 * q + j] = __float2bfloat16(vv[j] - __bfloat162float(hv));
                }
            }
        }
        __syncthreads();

        uint32_t a1h[4][4], a1l[4][4];
#pragma unroll
        for (int kt = 0; kt < 4; kt++) {
            uint32_t addr = sbase + SM_XH +
                (uint32_t)(wid * 16 + (lane & 15)) * 144u + (uint32_t)(kt * 16 + ((lane >> 4) << 3)) * 2u;
            ldsm4(a1h[kt], addr);
            ldsm4(a1l[kt], addr + (SM_XL - SM_XH));
        }

        float d2[8][4];
#pragma unroll
        for (int i = 0; i < 8; i++)
#pragma unroll
            for (int j = 0; j < 4; j++) d2[i][j] = 0.0f;

#pragma unroll 1
        for (int nc = 0; nc < 16; nc++) {
            float c0[4] = {0.f, 0.f, 0.f, 0.f}, c1[4] = {0.f, 0.f, 0.f, 0.f};
            uint32_t bb = sbase + SM_W1H +
                (uint32_t)(nc * 16 + (lane & 7) + ((lane >> 4) & 1) * 8) * 144u + ((lane >> 3) & 1) * 16u;
#pragma unroll
            for (int kt = 0; kt < 4; kt++) {
                uint32_t bh[4], bl[4];
                ldsm4(bh, bb + kt * 32u);
                ldsm4(bl, bb + kt * 32u + (SM_W1L - SM_W1H));
                mma16816(c0, a1h[kt], bh[0], bh[1]);
                mma16816(c1, a1h[kt], bh[2], bh[3]);
                mma16816(c0, a1h[kt], bl[0], bl[1]);
                mma16816(c1, a1h[kt], bl[2], bl[3]);
                mma16816(c0, a1l[kt], bh[0], bh[1]);
                mma16816(c1, a1l[kt], bh[2], bh[3]);
            }
            int cb = nc * 16 + (lane & 3) * 2;
            float2 bb0 = *(const float2*)&b1s[cb];
            float2 bb1 = *(const float2*)&b1s[cb + 8];
            float v00 = fmaxf(c0[0] + bb0.x, 0.f), v01 = fmaxf(c0[1] + bb0.y, 0.f);
            float v10 = fmaxf(c0[2] + bb0.x, 0.f), v11 = fmaxf(c0[3] + bb0.y, 0.f);
            float w00 = fmaxf(c1[0] + bb1.x, 0.f), w01 = fmaxf(c1[1] + bb1.y, 0.f);
            float w10 = fmaxf(c1[2] + bb1.x, 0.f), w11 = fmaxf(c1[3] + bb1.y, 0.f);
            uint32_t a2h[4], a2l[4];
            a2h[0] = packbf(v00, v01); a2l[0] = packbf(v00 - bf_lo(a2h[0]), v01 - bf_hi(a2h[0]));
            a2h[1] = packbf(v10, v11); a2l[1] = packbf(v10 - bf_lo(a2h[1]), v11 - bf_hi(a2h[1]));
            a2h[2] = packbf(w00, w01); a2l[2] = packbf(w00 - bf_lo(a2h[2]), w01 - bf_hi(a2h[2]));
            a2h[3] = packbf(w10, w11); a2l[3] = packbf(w10 - bf_lo(a2h[3]), w11 - bf_hi(a2h[3]));
            uint32_t b2b = sbase + SM_W2H +
                (uint32_t)((lane & 7) + ((lane >> 4) & 1) * 8) * 528u + (uint32_t)nc * 32u + ((lane >> 3) & 1) * 16u;
#pragma unroll
            for (int np = 0; np < 4; np++) {
                uint32_t bh[4], bl[4];
                ldsm4(bh, b2b + (uint32_t)np * (16u * 528u));
                ldsm4(bl, b2b + (uint32_t)np * (16u * 528u) + (SM_W2L - SM_W2H));
                mma16816(d2[2 * np],     a2h, bh[0], bh[1]);
                mma16816(d2[2 * np + 1], a2h, bh[2], bh[3]);
                mma16816(d2[2 * np],     a2h, bl[0], bl[1]);
                mma16816(d2[2 * np + 1], a2h, bl[2], bl[3]);
                mma16816(d2[2 * np],     a2l, bh[0], bh[1]);
                mma16816(d2[2 * np + 1], a2l, bh[2], bh[3]);
            }
        }

        int row0 = tile * MLP_TILE + wid * 16 + (lane >> 2);
        int colb = (lane & 3) * 2;
#pragma unroll
        for (int t = 0; t < 8; t++) {
            int col = t * 8 + colb;
            if (row0 < N_NODES) {
                float2 o;
                o.x = fmaxf(d2[t][0] + b2s[col], 0.f);
                o.y = fmaxf(d2[t][1] + b2s[col + 1], 0.f);
                *(float2*)(out + (size_t)row0 * 64 + col) = o;
            }
            if (row0 + 8 < N_NODES) {
                float2 o;
                o.x = fmaxf(d2[t][2] + b2s[col], 0.f);
                o.y = fmaxf(d2[t][3] + b2s[col + 1], 0.f);
                *(float2*)(out + (size_t)(row0 + 8) * 64 + col) = o;
            }
        }
        __syncthreads();
    }
}

// ---------------------------------------------------------------------------
// 5: BN column stats
// ---------------------------------------------------------------------------
__global__ void stats_kernel(const float* __restrict__ y) {
    __shared__ float ss[64], sq[64];
    if (threadIdx.x < 64) { ss[threadIdx.x] = 0.0f; sq[threadIdx.x] = 0.0f; }
    __syncthreads();
    const float4* y4 = (const float4*)y;
    const int total = N_NODES * 16;
    int i0 = blockIdx.x * 256 + threadIdx.x;
    int c4 = (i0 & 15) << 2;
    float4 s = make_float4(0.f, 0.f, 0.f, 0.f);
    float4 q = make_float4(0.f, 0.f, 0.f, 0.f);
    for (int i = i0; i < total; i += gridDim.x * 256) {
        float4 v = y4[i];
        s.x += v.x; s.y += v.y; s.z += v.z; s.w += v.w;
        q.x = fmaf(v.x, v.x, q.x);
        q.y = fmaf(v.y, v.y, q.y);
        q.z = fmaf(v.z, v.z, q.z);
        q.w = fmaf(v.w, v.w, q.w);
    }
    atomicAdd(&ss[c4 + 0], s.x); atomicAdd(&ss[c4 + 1], s.y);
    atomicAdd(&ss[c4 + 2], s.z); atomicAdd(&ss[c4 + 3], s.w);
    atomicAdd(&sq[c4 + 0], q.x); atomicAdd(&sq[c4 + 1], q.y);
    atomicAdd(&sq[c4 + 2], q.z); atomicAdd(&sq[c4 + 3], q.w);
    __syncthreads();
    if (threadIdx.x < 64) {
        atomicAdd(&g_colsum[threadIdx.x], ss[threadIdx.x]);
        atomicAdd(&g_colsq[threadIdx.x], sq[threadIdx.x]);
    }
}

// ---------------------------------------------------------------------------
// 6: BN apply in place
// ---------------------------------------------------------------------------
__global__ void bn_kernel(float* __restrict__ y,
                          const float* __restrict__ gamma,
                          const float* __restrict__ beta) {
    __shared__ float scale[64], shift[64];
    if (threadIdx.x < 64) {
        int c = threadIdx.x;
        const float invN = 1.0f / (float)N_NODES;
        float mean = g_colsum[c] * invN;
        float var = fmaxf(g_colsq[c] * invN - mean * mean, 0.0f);
        float sc = gamma[c] * rsqrtf(var + BN_EPS);
        scale[c] = sc;
        shift[c] = beta[c] - mean * sc;
    }
    __syncthreads();
    int i = blockIdx.x * blockDim.x + threadIdx.x;
    int stride = gridDim.x * blockDim.x;
    const int total4 = N_NODES * OUT_DIM / 4;
    float4* y4 = (float4*)y;
    for (; i < total4; i += stride) {
        int c4 = (i & 15) * 4;
        float4 v = y4[i];
        v.x = fmaf(v.x, scale[c4 + 0], shift[c4 + 0]);
        v.y = fmaf(v.y, scale[c4 + 1], shift[c4 + 1]);
        v.z = fmaf(v.z, scale[c4 + 2], shift[c4 + 2]);
        v.w = fmaf(v.w, scale[c4 + 3], shift[c4 + 3]);
        y4[i] = v;
    }
}

// ---------------------------------------------------------------------------
extern "C" void kernel_launch(void* const* d_in, const int* in_sizes, int n_in,
                              void* d_out, int out_size) {
    const float* h     = (const float*)d_in[0];
    const float* W1    = (const float*)d_in[1];
    const float* b1    = (const float*)d_in[2];
    const float* W2    = (const float*)d_in[3];
    const float* b2    = (const float*)d_in[4];
    const float* gamma = (const float*)d_in[5];
    const float* beta  = (const float*)d_in[6];
    const int*   src   = (const int*)d_in[7];
    const int*   dst   = (const int*)d_in[8];
    float* out = (float*)d_out;

    cudaFuncSetAttribute(mlp_mma_kernel, cudaFuncAttributeMaxDynamicSharedMemorySize, SMEM_MLP);

    zero_kernel<<<(N_NODES + 255) / 256, 256>>>();
    scatter_kernel<<<(N_EDGES + 255) / 256, 256>>>(src, dst);
    agg_kernel<<<(N_NODES * 32 + 255) / 256, 256>>>(h);
    mlp_mma_kernel<<<148, 512, SMEM_MLP>>>(W1, b1, W2, b2, out);
    stats_kernel<<<1024, 256>>>(out);
    bn_kernel<<<2048, 256>>>(out, gamma, beta);
}